// round 13
// baseline (speedup 1.0000x reference)
#include <cuda_runtime.h>
#include <cuda_fp16.h>
#include <cstdint>

// ---------------------------------------------------------------------------
// Problem constants
// ---------------------------------------------------------------------------
#define NB      2
#define C_IN    16
#define NN      4096
#define TT      12
#define C_OUT   16
#define GDEP    2
#define ALPHA   0.05f

#define COLS    384
#define PN      96
#define HSZ     (NN * COLS)
#define PSZ     ((size_t)NN * PN)
#define MSZ     ((size_t)NN * NN)

// GEMM tiling (fp16, 2 CTAs/SM) — R8 tile
#define BM      128
#define BN      96
#define BK      32
#define PADH    40
#define STAGE_H ((BM + BN) * PADH)
#define SM_BYTES (3 * STAGE_H * 2)       // 53760

// persistent scheduling
#define NCTA    296
#define NJOBS   384
#define NTJ     128
#define TOTAL_U (NJOBS * NTJ)

// fused transpose kernels: smem float tile [4][96][33]
#define XP_SMEM (4 * 96 * 33 * 4)        // 50688
#define T3(t, q, c, v) t[((q) * 96 + (c)) * 33 + (v)]

// ---------------------------------------------------------------------------
// Device scratch
// ---------------------------------------------------------------------------
__device__ float  g_Hs[GDEP + 1][HSZ];
__device__ float  g_G[12][PSZ];
__device__ __half g_Ah[6 * MSZ];
__device__ __half g_Xp[6 * PSZ];

// A combos: 0=Ar, 1=Ai', 2=Ar+Ai', 3=Aj', 4=Ak', 5=Aj'+Ak'   (X'=(X+I)/rowsum)
// B panels: 0=xr, 1=xi-xr, 2=xr+xi, 3=xj, 4=xj+xk, 5=xj-xk
__constant__ int c_Aidx[12] = {2, 0, 1, 5, 3, 4, 2, 0, 1, 5, 3, 4};
__constant__ int c_Bidx[12] = {0, 1, 2, 3, 4, 5, 3, 5, 4, 0, 2, 1};

// ---------------------------------------------------------------------------
// helpers
// ---------------------------------------------------------------------------
__device__ __forceinline__ uint32_t smem_u32(const void* p) {
    uint32_t a;
    asm("{ .reg .u64 t; cvta.to.shared.u64 t, %1; cvt.u32.u64 %0, t; }"
        : "=r"(a) : "l"(p));
    return a;
}
__device__ __forceinline__ void cp_async16(uint32_t dst, const void* src) {
    asm volatile("cp.async.cg.shared.global [%0], [%1], 16;"
                 :: "r"(dst), "l"(src) : "memory");
}
__device__ __forceinline__ void cp_commit() {
    asm volatile("cp.async.commit_group;" ::: "memory");
}
__device__ __forceinline__ void cp_wait1() {
    asm volatile("cp.async.wait_group 1;" ::: "memory");
}
__device__ __forceinline__ void cp_wait0() {
    asm volatile("cp.async.wait_group 0;" ::: "memory");
}
__device__ __forceinline__ void ldsm_x4(uint32_t* r, uint32_t addr) {
    asm volatile(
        "ldmatrix.sync.aligned.m8n8.x4.shared.b16 {%0,%1,%2,%3}, [%4];"
        : "=r"(r[0]), "=r"(r[1]), "=r"(r[2]), "=r"(r[3]) : "r"(addr));
}
__device__ __forceinline__ void mma_f16(float* c, const uint32_t* a,
                                        const uint32_t* b) {
    asm volatile(
        "mma.sync.aligned.m16n8k16.row.col.f32.f16.f16.f32 "
        "{%0,%1,%2,%3}, {%4,%5,%6,%7}, {%8,%9}, {%0,%1,%2,%3};"
        : "+f"(c[0]), "+f"(c[1]), "+f"(c[2]), "+f"(c[3])
        : "r"(a[0]), "r"(a[1]), "r"(a[2]), "r"(a[3]), "r"(b[0]), "r"(b[1]));
}

// panel emit from smem tile (stage 2 of both fused kernels)
__device__ __forceinline__ void emit_panels(const float* t, int w0, int tid) {
    const int tx = tid & 31, ty = tid >> 5;
    for (int c = ty; c < 96; c += 8) {
        const float xr = T3(t, 0, c, tx);
        const float xi = T3(t, 1, c, tx);
        const float xj = T3(t, 2, c, tx);
        const float xk = T3(t, 3, c, tx);
        const size_t o = (size_t)c * NN + w0 + tx;
        g_Xp[0 * PSZ + o] = __float2half_rn(xr);
        g_Xp[1 * PSZ + o] = __float2half_rn(xi - xr);
        g_Xp[2 * PSZ + o] = __float2half_rn(xr + xi);
        g_Xp[3 * PSZ + o] = __float2half_rn(xj);
        g_Xp[4 * PSZ + o] = __float2half_rn(xj + xk);
        g_Xp[5 * PSZ + o] = __float2half_rn(xj - xk);
    }
}

// ---------------------------------------------------------------------------
// 1) fused prepass: rowsums + 6 fp16 A combos, one pass over inputs.
// ---------------------------------------------------------------------------
__global__ void __launch_bounds__(256)
prep_kernel(const float* __restrict__ Ar, const float* __restrict__ Ai,
            const float* __restrict__ Aj, const float* __restrict__ Ak) {
    const int row  = blockIdx.x;
    const int pair = blockIdx.y;
    const float* P = pair ? Aj : Ar;
    const float* Q = pair ? Ak : Ai;
    const float* rp = P + (size_t)row * NN;
    const float* rq = Q + (size_t)row * NN;

    __shared__ float sp[NN];
    __shared__ float sq[NN];
    __shared__ float redP[8], redQ[8], s_inv[2];

    float sumP = 0.0f, sumQ = 0.0f;
    for (int k = threadIdx.x * 4; k < NN; k += 1024) {
        float4 v = *(const float4*)&rp[k];
        *(float4*)&sp[k] = v;
        sumP += v.x + v.y + v.z + v.w;
        float4 w = *(const float4*)&rq[k];
        *(float4*)&sq[k] = w;
        sumQ += w.x + w.y + w.z + w.w;
    }
    #pragma unroll
    for (int o = 16; o > 0; o >>= 1) {
        sumP += __shfl_xor_sync(0xffffffffu, sumP, o);
        sumQ += __shfl_xor_sync(0xffffffffu, sumQ, o);
    }
    if ((threadIdx.x & 31) == 0) {
        redP[threadIdx.x >> 5] = sumP;
        redQ[threadIdx.x >> 5] = sumQ;
    }
    __syncthreads();
    if (threadIdx.x == 0) {
        float tp = 0.0f, tq = 0.0f;
        #pragma unroll
        for (int i = 0; i < 8; i++) { tp += redP[i]; tq += redQ[i]; }
        s_inv[0] = 1.0f / (tp + 1.0f);
        s_inv[1] = 1.0f / (tq + 1.0f);
    }
    __syncthreads();
    const float invP = s_inv[0], invQ = s_inv[1];

    __half* o0 = g_Ah + (size_t)(pair ? 3 : 0) * MSZ + (size_t)row * NN;
    __half* o1 = o0 + MSZ;
    __half* o2 = o1 + MSZ;

    for (int k = threadIdx.x * 4; k < NN; k += 1024) {
        __half h0[4], h1[4], h2[4];
        #pragma unroll
        for (int u = 0; u < 4; u++) {
            const float ii = ((k + u) == row) ? 1.0f : 0.0f;
            const float p = sp[k + u];
            const float q = sq[k + u];
            float v0, v1;
            if (pair == 0) {
                v0 = p;                       // Ar
                v1 = (q + ii) * invQ;         // Ai'
            } else {
                v0 = (p + ii) * invP;         // Aj'
                v1 = (q + ii) * invQ;         // Ak'
            }
            h0[u] = __float2half_rn(v0);
            h1[u] = __float2half_rn(v1);
            h2[u] = __float2half_rn(v0 + v1);
        }
        *(uint2*)&o0[k] = *(uint2*)h0;
        *(uint2*)&o1[k] = *(uint2*)h1;
        *(uint2*)&o2[k] = *(uint2*)h2;
    }
}

// ---------------------------------------------------------------------------
// 2) fused pack+xpose: x -> h0 [w][col] AND 6 fp16 B panels [c][w]
// ---------------------------------------------------------------------------
__global__ void __launch_bounds__(256)
pack0_kernel(const float* __restrict__ x) {
    extern __shared__ float t[];
    const int w0 = blockIdx.x * 32;
    const int tid = threadIdx.x;

    #pragma unroll
    for (int i = 0; i < 48; i++) {
        const int e = tid + i * 256;          // 0..12287 over 32w x 384col
        const int v = e / 384, col = e - v * 384;
        const int q = col / 96, rem = col - q * 96;
        const int bc = rem / 12, tt = rem - bc * 12;
        const int b = bc >> 2, c = bc & 3;
        const float val =
            x[(((size_t)b * C_IN + q * 4 + c) * NN + w0 + v) * TT + tt];
        g_Hs[0][(size_t)(w0 + v) * COLS + col] = val;
        T3(t, q, rem, v) = val;
    }
    __syncthreads();
    emit_panels(t, w0, tid);
}

// ---------------------------------------------------------------------------
// 3) zero G panels (once, before first qgemm)
// ---------------------------------------------------------------------------
__global__ void yzero_kernel() {
    const size_t idx = ((size_t)blockIdx.x * blockDim.x + threadIdx.x) * 4;
    if (idx < 12 * PSZ)
        *(float4*)&g_G[0][idx] = make_float4(0.f, 0.f, 0.f, 0.f);
}

// ---------------------------------------------------------------------------
// 4) persistent fp16 GEMM (unchanged from R12)
// ---------------------------------------------------------------------------
__global__ void __launch_bounds__(128, 2)
qgemm_kernel() {
    extern __shared__ __half sm[];
    const uint32_t sbase = smem_u32(sm);

    const int tid = threadIdx.x;
    const int wid = tid >> 5, lane = tid & 31;
    const int wm  = (wid & 1) * 64;
    const int wn  = (wid >> 1) * 48;
    const int lg  = lane >> 2, tq = lane & 3;
    const int r8  = lane & 7, sub = lane >> 3;

    uint32_t aoff[4], boff[3];
    #pragma unroll
    for (int i = 0; i < 4; i++)
        aoff[i] = (uint32_t)((wm + i * 16 + (sub & 1) * 8 + r8) * PADH * 2
                             + (sub >> 1) * 16);
    #pragma unroll
    for (int p = 0; p < 3; p++)
        boff[p] = (uint32_t)((BM + wn + p * 16 + (sub >> 1) * 8 + r8) * PADH * 2
                             + (sub & 1) * 16);

    float acc[4][6][4];
    #pragma unroll
    for (int i = 0; i < 4; i++)
        #pragma unroll
        for (int j = 0; j < 6; j++)
            #pragma unroll
            for (int r = 0; r < 4; r++) acc[i][j][r] = 0.0f;

    int u        = (int)(((long long)blockIdx.x * TOTAL_U) / NCTA);
    const int ue = (int)(((long long)(blockIdx.x + 1) * TOTAL_U) / NCTA);

    while (u < ue) {
        const int job  = u / NTJ;
        const int kt0  = u - job * NTJ;
        const int nseg = min(NTJ - kt0, ue - u);
        const int g    = job >> 5;
        const int mt   = job & 31;

        const __half* __restrict__ Ag0 =
            g_Ah + (size_t)c_Aidx[g] * MSZ + (size_t)(mt * BM) * NN;
        const __half* __restrict__ Bg0 = g_Xp + (size_t)c_Bidx[g] * PSZ;

        auto load_stage = [&](int st, int kb) {
            const uint32_t ao = sbase + (uint32_t)(st * STAGE_H) * 2;
            const uint32_t bo = ao + (uint32_t)(BM * PADH) * 2;
            #pragma unroll
            for (int c = tid; c < 512; c += 128) {
                const int row = c >> 2, seg = c & 3;
                cp_async16(ao + (uint32_t)(row * PADH * 2 + seg * 16),
                           Ag0 + (size_t)row * NN + kb + seg * 8);
            }
            #pragma unroll
            for (int c = tid; c < 384; c += 128) {
                const int row = c >> 2, seg = c & 3;
                cp_async16(bo + (uint32_t)(row * PADH * 2 + seg * 16),
                           Bg0 + (size_t)row * NN + kb + seg * 8);
            }
        };

        cp_wait0();
        __syncthreads();
        load_stage(0, kt0 * BK);
        cp_commit();
        if (nseg > 1) load_stage(1, (kt0 + 1) * BK);
        cp_commit();

        for (int it = 0; it < nseg; it++) {
            cp_wait1();
            __syncthreads();
            if (it + 2 < nseg) load_stage((it + 2) % 3, (kt0 + it + 2) * BK);
            cp_commit();

            const uint32_t stage = sbase + (uint32_t)((it % 3) * STAGE_H) * 2;
            #pragma unroll
            for (int kk = 0; kk < 2; kk++) {
                const uint32_t kb = stage + kk * 32;
                uint32_t af[4][4], bfr[12];
                ldsm_x4(af[0], kb + aoff[0]);
                ldsm_x4(af[1], kb + aoff[1]);
                ldsm_x4(af[2], kb + aoff[2]);
                ldsm_x4(af[3], kb + aoff[3]);
                ldsm_x4(&bfr[0], kb + boff[0]);
                ldsm_x4(&bfr[4], kb + boff[1]);
                ldsm_x4(&bfr[8], kb + boff[2]);
                #pragma unroll
                for (int i = 0; i < 4; i++)
                    #pragma unroll
                    for (int j = 0; j < 6; j++)
                        mma_f16(acc[i][j], af[i], &bfr[j * 2]);
            }
        }

        float* Gp = g_G[g] + (size_t)(mt * BM) * PN;
        #pragma unroll
        for (int i = 0; i < 4; i++) {
            const int r0 = wm + i * 16 + lg;
            #pragma unroll
            for (int j = 0; j < 6; j++) {
                const int c0 = wn + j * 8 + 2 * tq;
                atomicAdd(&Gp[(size_t)r0 * PN + c0],       acc[i][j][0]);
                atomicAdd(&Gp[(size_t)r0 * PN + c0 + 1],   acc[i][j][1]);
                atomicAdd(&Gp[(size_t)(r0 + 8) * PN + c0],     acc[i][j][2]);
                atomicAdd(&Gp[(size_t)(r0 + 8) * PN + c0 + 1], acc[i][j][3]);
                acc[i][j][0] = acc[i][j][1] = acc[i][j][2] = acc[i][j][3] = 0.0f;
            }
        }
        u += nseg;
    }
}

// ---------------------------------------------------------------------------
// 5) fused combine(s=0)+xpose+yzero: G -> h1 + 6 panels, G zeroed in place
//    out_r = G0-G2-G3+G5   out_i = G0+G1-G3+G4
//    out_j = G6-G8+G9+G11  out_k = G6-G7+G9-G10
// ---------------------------------------------------------------------------
__global__ void __launch_bounds__(256)
combxp_kernel() {
    extern __shared__ float t[];
    const int w0 = blockIdx.x * 32;
    const int tid = threadIdx.x;
    const float* __restrict__ H0 = g_Hs[0];
    float* __restrict__ Hn = g_Hs[1];

    #pragma unroll
    for (int i = 0; i < 12; i++) {
        const int e = tid + i * 256;          // 0..3071 over 32v x 96c
        const int v = e / 96, c = e - v * 96;
        const size_t o = (size_t)(w0 + v) * PN + c;

        float G[12];
        #pragma unroll
        for (int g = 0; g < 12; g++) {
            G[g] = g_G[g][o];
            g_G[g][o] = 0.0f;                 // ready for qgemm(s=1)
        }
        const float out_r = G[0] - G[2] - G[3] + G[5];
        const float out_i = G[0] + G[1] - G[3] + G[4];
        const float out_j = G[6] - G[8] + G[9] + G[11];
        const float out_k = G[6] - G[7] + G[9] - G[10];

        const size_t base = (size_t)(w0 + v) * COLS + c;
        const float hr = ALPHA * H0[base + 0 * 96] + (1.0f - ALPHA) * out_r;
        const float hi = ALPHA * H0[base + 1 * 96] + (1.0f - ALPHA) * out_i;
        const float hj = ALPHA * H0[base + 2 * 96] + (1.0f - ALPHA) * out_j;
        const float hk = ALPHA * H0[base + 3 * 96] + (1.0f - ALPHA) * out_k;
        Hn[base + 0 * 96] = hr;
        Hn[base + 1 * 96] = hi;
        Hn[base + 2 * 96] = hj;
        Hn[base + 3 * 96] = hk;
        T3(t, 0, c, v) = hr;
        T3(t, 1, c, v) = hi;
        T3(t, 2, c, v) = hj;
        T3(t, 3, c, v) = hk;
    }
    __syncthreads();
    emit_panels(t, w0, tid);
}

// ---------------------------------------------------------------------------
// 6) plain combine for s=1 (writes h2 only)
// ---------------------------------------------------------------------------
__global__ void combine_kernel(int s) {
    int idx = blockIdx.x * blockDim.x + threadIdx.x;
    if (idx >= NN * PN) return;
    const int v = idx / PN;
    const int c = idx - v * PN;
    const size_t o = (size_t)v * PN + c;

    const float G0 = g_G[0][o],  G1 = g_G[1][o],  G2 = g_G[2][o];
    const float G3 = g_G[3][o],  G4 = g_G[4][o],  G5 = g_G[5][o];
    const float G6 = g_G[6][o],  G7 = g_G[7][o],  G8 = g_G[8][o];
    const float G9 = g_G[9][o],  G10 = g_G[10][o], G11 = g_G[11][o];

    const float out_r = G0 - G2 - G3 + G5;
    const float out_i = G0 + G1 - G3 + G4;
    const float out_j = G6 - G8 + G9 + G11;
    const float out_k = G6 - G7 + G9 - G10;

    const size_t base = (size_t)v * COLS + c;
    const float* __restrict__ H0 = g_Hs[0];
    float* __restrict__ Hn = g_Hs[s + 1];
    Hn[base + 0 * 96] = ALPHA * H0[base + 0 * 96] + (1.0f - ALPHA) * out_r;
    Hn[base + 1 * 96] = ALPHA * H0[base + 1 * 96] + (1.0f - ALPHA) * out_i;
    Hn[base + 2 * 96] = ALPHA * H0[base + 2 * 96] + (1.0f - ALPHA) * out_j;
    Hn[base + 3 * 96] = ALPHA * H0[base + 3 * 96] + (1.0f - ALPHA) * out_k;
}

// ---------------------------------------------------------------------------
// 7) final quaternion-weight projection
// ---------------------------------------------------------------------------
__global__ void project_kernel(const float* __restrict__ weight,
                               float* __restrict__ out) {
    __shared__ float ham[GDEP + 1][16][16];
    const int   widx[4][4] = {{0,1,2,3},{1,0,3,2},{2,3,0,1},{3,2,1,0}};
    const float sgn[4][4]  = {{ 1.f,-1.f,-1.f,-1.f},
                              { 1.f, 1.f,-1.f, 1.f},
                              { 1.f, 1.f, 1.f,-1.f},
                              { 1.f,-1.f, 1.f, 1.f}};
    for (int idx = threadIdx.x; idx < (GDEP + 1) * 256; idx += blockDim.x) {
        const int k  = idx >> 8;
        const int i  = (idx >> 4) & 15;
        const int j  = idx & 15;
        const int qi = i >> 2, a = i & 3;
        const int qj = j >> 2, bb = j & 3;
        ham[k][i][j] = sgn[qj][qi] * weight[(k * 4 + a) * 16 + widx[qj][qi] * 4 + bb];
    }
    __syncthreads();

    const int gidx = blockIdx.x * blockDim.x + threadIdx.x;
    if (gidx >= NB * NN * TT) return;
    const int t = gidx % TT;
    const int n = (gidx / TT) % NN;
    const int b = gidx / (TT * NN);

    float hv[(GDEP + 1) * 16];
    #pragma unroll
    for (int k = 0; k <= GDEP; k++)
        #pragma unroll
        for (int i = 0; i < 16; i++)
            hv[k * 16 + i] =
                g_Hs[k][(size_t)n * COLS + (i >> 2) * 96 + (b * 4 + (i & 3)) * 12 + t];

    #pragma unroll
    for (int j = 0; j < 16; j++) {
        float acc = 0.0f;
        #pragma unroll
        for (int k = 0; k <= GDEP; k++)
            #pragma unroll
            for (int i = 0; i < 16; i++)
                acc += hv[k * 16 + i] * ham[k][i][j];
        out[(((size_t)b * C_OUT + j) * NN + n) * TT + t] = acc;
    }
}

// ---------------------------------------------------------------------------
extern "C" void kernel_launch(void* const* d_in, const int* in_sizes, int n_in,
                              void* d_out, int out_size) {
    const float* x  = (const float*)d_in[0];
    const float* Ar = (const float*)d_in[1];
    const float* Ai = (const float*)d_in[2];
    const float* Aj = (const float*)d_in[3];
    const float* Ak = (const float*)d_in[4];
    const float* w  = (const float*)d_in[5];
    float* out = (float*)d_out;

    cudaFuncSetAttribute(qgemm_kernel,
                         cudaFuncAttributeMaxDynamicSharedMemorySize, SM_BYTES);
    cudaFuncSetAttribute(pack0_kernel,
                         cudaFuncAttributeMaxDynamicSharedMemorySize, XP_SMEM);
    cudaFuncSetAttribute(combxp_kernel,
                         cudaFuncAttributeMaxDynamicSharedMemorySize, XP_SMEM);

    yzero_kernel<<<(12 * (int)PSZ / 4 + 255) / 256, 256>>>();
    prep_kernel<<<dim3(NN, 2), 256>>>(Ar, Ai, Aj, Ak);
    pack0_kernel<<<NN / 32, 256, XP_SMEM>>>(x);
    qgemm_kernel<<<NCTA, 128, SM_BYTES>>>();
    combxp_kernel<<<NN / 32, 256, XP_SMEM>>>();
    qgemm_kernel<<<NCTA, 128, SM_BYTES>>>();
    combine_kernel<<<(NN * PN + 255) / 256, 256>>>(1);
    project_kernel<<<(NB * NN * TT + 255) / 256, 256>>>(w, out);
}

// round 14
// speedup vs baseline: 1.2682x; 1.2682x over previous
#include <cuda_runtime.h>
#include <cuda_fp16.h>
#include <cstdint>

// ---------------------------------------------------------------------------
// Problem constants
// ---------------------------------------------------------------------------
#define NB      2
#define C_IN    16
#define NN      4096
#define TT      12
#define C_OUT   16
#define GDEP    2
#define ALPHA   0.05f

#define COLS    384
#define PN      96
#define HSZ     (NN * COLS)
#define PSZ     ((size_t)NN * PN)
#define MSZ     ((size_t)NN * NN)

// GEMM tiling (fp16, 2 CTAs/SM) — R8 tile
#define BM      128
#define BN      96
#define BK      32
#define PADH    40
#define STAGE_H ((BM + BN) * PADH)
#define SM_BYTES (3 * STAGE_H * 2)       // 53760

// persistent scheduling
#define NCTA    296
#define NJOBS   384
#define NTJ     128
#define TOTAL_U (NJOBS * NTJ)

// ---------------------------------------------------------------------------
// Device scratch
// ---------------------------------------------------------------------------
__device__ float  g_Hs[GDEP + 1][HSZ];
__device__ float  g_G[12][PSZ];
__device__ __half g_Ah[6 * MSZ];
__device__ __half g_Xp[6 * PSZ];

// A combos: 0=Ar, 1=Ai', 2=Ar+Ai', 3=Aj', 4=Ak', 5=Aj'+Ak'   (X'=(X+I)/rowsum)
// B panels: 0=xr, 1=xi-xr, 2=xr+xi, 3=xj, 4=xj+xk, 5=xj-xk
__constant__ int c_Aidx[12] = {2, 0, 1, 5, 3, 4, 2, 0, 1, 5, 3, 4};
__constant__ int c_Bidx[12] = {0, 1, 2, 3, 4, 5, 3, 5, 4, 0, 2, 1};

// ---------------------------------------------------------------------------
// helpers
// ---------------------------------------------------------------------------
__device__ __forceinline__ uint32_t smem_u32(const void* p) {
    uint32_t a;
    asm("{ .reg .u64 t; cvta.to.shared.u64 t, %1; cvt.u32.u64 %0, t; }"
        : "=r"(a) : "l"(p));
    return a;
}
__device__ __forceinline__ void cp_async16(uint32_t dst, const void* src) {
    asm volatile("cp.async.cg.shared.global [%0], [%1], 16;"
                 :: "r"(dst), "l"(src) : "memory");
}
__device__ __forceinline__ void cp_commit() {
    asm volatile("cp.async.commit_group;" ::: "memory");
}
__device__ __forceinline__ void cp_wait1() {
    asm volatile("cp.async.wait_group 1;" ::: "memory");
}
__device__ __forceinline__ void cp_wait0() {
    asm volatile("cp.async.wait_group 0;" ::: "memory");
}
__device__ __forceinline__ void ldsm_x4(uint32_t* r, uint32_t addr) {
    asm volatile(
        "ldmatrix.sync.aligned.m8n8.x4.shared.b16 {%0,%1,%2,%3}, [%4];"
        : "=r"(r[0]), "=r"(r[1]), "=r"(r[2]), "=r"(r[3]) : "r"(addr));
}
__device__ __forceinline__ void mma_f16(float* c, const uint32_t* a,
                                        const uint32_t* b) {
    asm volatile(
        "mma.sync.aligned.m16n8k16.row.col.f32.f16.f16.f32 "
        "{%0,%1,%2,%3}, {%4,%5,%6,%7}, {%8,%9}, {%0,%1,%2,%3};"
        : "+f"(c[0]), "+f"(c[1]), "+f"(c[2]), "+f"(c[3])
        : "r"(a[0]), "r"(a[1]), "r"(a[2]), "r"(a[3]), "r"(b[0]), "r"(b[1]));
}

// ---------------------------------------------------------------------------
// 1) fused prepass: rowsums + 6 fp16 A combos, one pass over inputs.
// ---------------------------------------------------------------------------
__global__ void __launch_bounds__(256)
prep_kernel(const float* __restrict__ Ar, const float* __restrict__ Ai,
            const float* __restrict__ Aj, const float* __restrict__ Ak) {
    const int row  = blockIdx.x;
    const int pair = blockIdx.y;
    const float* P = pair ? Aj : Ar;
    const float* Q = pair ? Ak : Ai;
    const float* rp = P + (size_t)row * NN;
    const float* rq = Q + (size_t)row * NN;

    __shared__ float sp[NN];
    __shared__ float sq[NN];
    __shared__ float redP[8], redQ[8], s_inv[2];

    float sumP = 0.0f, sumQ = 0.0f;
    for (int k = threadIdx.x * 4; k < NN; k += 1024) {
        float4 v = *(const float4*)&rp[k];
        *(float4*)&sp[k] = v;
        sumP += v.x + v.y + v.z + v.w;
        float4 w = *(const float4*)&rq[k];
        *(float4*)&sq[k] = w;
        sumQ += w.x + w.y + w.z + w.w;
    }
    #pragma unroll
    for (int o = 16; o > 0; o >>= 1) {
        sumP += __shfl_xor_sync(0xffffffffu, sumP, o);
        sumQ += __shfl_xor_sync(0xffffffffu, sumQ, o);
    }
    if ((threadIdx.x & 31) == 0) {
        redP[threadIdx.x >> 5] = sumP;
        redQ[threadIdx.x >> 5] = sumQ;
    }
    __syncthreads();
    if (threadIdx.x == 0) {
        float tp = 0.0f, tq = 0.0f;
        #pragma unroll
        for (int i = 0; i < 8; i++) { tp += redP[i]; tq += redQ[i]; }
        s_inv[0] = 1.0f / (tp + 1.0f);
        s_inv[1] = 1.0f / (tq + 1.0f);
    }
    __syncthreads();
    const float invP = s_inv[0], invQ = s_inv[1];

    __half* o0 = g_Ah + (size_t)(pair ? 3 : 0) * MSZ + (size_t)row * NN;
    __half* o1 = o0 + MSZ;
    __half* o2 = o1 + MSZ;

    for (int k = threadIdx.x * 4; k < NN; k += 1024) {
        __half h0[4], h1[4], h2[4];
        #pragma unroll
        for (int u = 0; u < 4; u++) {
            const float ii = ((k + u) == row) ? 1.0f : 0.0f;
            const float p = sp[k + u];
            const float q = sq[k + u];
            float v0, v1;
            if (pair == 0) {
                v0 = p;                       // Ar
                v1 = (q + ii) * invQ;         // Ai'
            } else {
                v0 = (p + ii) * invP;         // Aj'
                v1 = (q + ii) * invQ;         // Ak'
            }
            h0[u] = __float2half_rn(v0);
            h1[u] = __float2half_rn(v1);
            h2[u] = __float2half_rn(v0 + v1);
        }
        *(uint2*)&o0[k] = *(uint2*)h0;
        *(uint2*)&o1[k] = *(uint2*)h1;
        *(uint2*)&o2[k] = *(uint2*)h2;
    }
}

// ---------------------------------------------------------------------------
// 2) pack x -> g_Hs[0][w][col], col = q*96 + (b*4+c)*12 + t
// ---------------------------------------------------------------------------
__global__ void pack_kernel(const float* __restrict__ x) {
    int idx = blockIdx.x * blockDim.x + threadIdx.x;
    if (idx >= HSZ) return;
    int w   = idx / COLS;
    int col = idx - w * COLS;
    int q   = col / 96;
    int rem = col - q * 96;
    int bc  = rem / 12;
    int t   = rem - bc * 12;
    int b   = bc >> 2;
    int c   = bc & 3;
    g_Hs[0][idx] = x[(((size_t)b * C_IN + (q * 4 + c)) * NN + w) * TT + t];
}

// ---------------------------------------------------------------------------
// 3) transpose + combo + fp16: g_Hs[s] -> 6 B panels [c96][w]
// ---------------------------------------------------------------------------
__global__ void xpose_kernel(int s) {
    __shared__ float t4[4][32][33];
    const float* __restrict__ H = g_Hs[s];
    const int w0 = blockIdx.x * 32, c0 = blockIdx.y * 32;
    const int tx = threadIdx.x, ty = threadIdx.y;  // (32, 8)
    #pragma unroll
    for (int q = 0; q < 4; q++)
        #pragma unroll
        for (int i = 0; i < 32; i += 8)
            t4[q][ty + i][tx] = H[(size_t)(w0 + ty + i) * COLS + q * 96 + c0 + tx];
    __syncthreads();
    #pragma unroll
    for (int i = 0; i < 32; i += 8) {
        const float xr = t4[0][tx][ty + i];
        const float xi = t4[1][tx][ty + i];
        const float xj = t4[2][tx][ty + i];
        const float xk = t4[3][tx][ty + i];
        const size_t o = (size_t)(c0 + ty + i) * NN + w0 + tx;
        g_Xp[0 * PSZ + o] = __float2half_rn(xr);
        g_Xp[1 * PSZ + o] = __float2half_rn(xi - xr);
        g_Xp[2 * PSZ + o] = __float2half_rn(xr + xi);
        g_Xp[3 * PSZ + o] = __float2half_rn(xj);
        g_Xp[4 * PSZ + o] = __float2half_rn(xj + xk);
        g_Xp[5 * PSZ + o] = __float2half_rn(xj - xk);
    }
}

// ---------------------------------------------------------------------------
// 4) zero G panels (once, before first qgemm; combine(s=0) re-zeroes in place)
// ---------------------------------------------------------------------------
__global__ void yzero_kernel() {
    const size_t idx = ((size_t)blockIdx.x * blockDim.x + threadIdx.x) * 4;
    if (idx < 12 * PSZ)
        *(float4*)&g_G[0][idx] = make_float4(0.f, 0.f, 0.f, 0.f);
}

// ---------------------------------------------------------------------------
// 5) persistent fp16 GEMM: balanced split-K; plain store for full-job CTAs
// ---------------------------------------------------------------------------
__global__ void __launch_bounds__(128, 2)
qgemm_kernel() {
    extern __shared__ __half sm[];
    const uint32_t sbase = smem_u32(sm);

    const int tid = threadIdx.x;
    const int wid = tid >> 5, lane = tid & 31;
    const int wm  = (wid & 1) * 64;
    const int wn  = (wid >> 1) * 48;
    const int lg  = lane >> 2, tq = lane & 3;
    const int r8  = lane & 7, sub = lane >> 3;

    uint32_t aoff[4], boff[3];
    #pragma unroll
    for (int i = 0; i < 4; i++)
        aoff[i] = (uint32_t)((wm + i * 16 + (sub & 1) * 8 + r8) * PADH * 2
                             + (sub >> 1) * 16);
    #pragma unroll
    for (int p = 0; p < 3; p++)
        boff[p] = (uint32_t)((BM + wn + p * 16 + (sub >> 1) * 8 + r8) * PADH * 2
                             + (sub & 1) * 16);

    float acc[4][6][4];
    #pragma unroll
    for (int i = 0; i < 4; i++)
        #pragma unroll
        for (int j = 0; j < 6; j++)
            #pragma unroll
            for (int r = 0; r < 4; r++) acc[i][j][r] = 0.0f;

    int u        = (int)(((long long)blockIdx.x * TOTAL_U) / NCTA);
    const int ue = (int)(((long long)(blockIdx.x + 1) * TOTAL_U) / NCTA);

    while (u < ue) {
        const int job  = u / NTJ;
        const int kt0  = u - job * NTJ;
        const int nseg = min(NTJ - kt0, ue - u);
        const int g    = job >> 5;
        const int mt   = job & 31;

        const __half* __restrict__ Ag0 =
            g_Ah + (size_t)c_Aidx[g] * MSZ + (size_t)(mt * BM) * NN;
        const __half* __restrict__ Bg0 = g_Xp + (size_t)c_Bidx[g] * PSZ;

        auto load_stage = [&](int st, int kb) {
            const uint32_t ao = sbase + (uint32_t)(st * STAGE_H) * 2;
            const uint32_t bo = ao + (uint32_t)(BM * PADH) * 2;
            #pragma unroll
            for (int c = tid; c < 512; c += 128) {
                const int row = c >> 2, seg = c & 3;
                cp_async16(ao + (uint32_t)(row * PADH * 2 + seg * 16),
                           Ag0 + (size_t)row * NN + kb + seg * 8);
            }
            #pragma unroll
            for (int c = tid; c < 384; c += 128) {
                const int row = c >> 2, seg = c & 3;
                cp_async16(bo + (uint32_t)(row * PADH * 2 + seg * 16),
                           Bg0 + (size_t)row * NN + kb + seg * 8);
            }
        };

        cp_wait0();
        __syncthreads();
        load_stage(0, kt0 * BK);
        cp_commit();
        if (nseg > 1) load_stage(1, (kt0 + 1) * BK);
        cp_commit();

        for (int it = 0; it < nseg; it++) {
            cp_wait1();
            __syncthreads();
            if (it + 2 < nseg) load_stage((it + 2) % 3, (kt0 + it + 2) * BK);
            cp_commit();

            const uint32_t stage = sbase + (uint32_t)((it % 3) * STAGE_H) * 2;
            #pragma unroll
            for (int kk = 0; kk < 2; kk++) {
                const uint32_t kb = stage + kk * 32;
                uint32_t af[4][4], bfr[12];
                ldsm_x4(af[0], kb + aoff[0]);
                ldsm_x4(af[1], kb + aoff[1]);
                ldsm_x4(af[2], kb + aoff[2]);
                ldsm_x4(af[3], kb + aoff[3]);
                ldsm_x4(&bfr[0], kb + boff[0]);
                ldsm_x4(&bfr[4], kb + boff[1]);
                ldsm_x4(&bfr[8], kb + boff[2]);
                #pragma unroll
                for (int i = 0; i < 4; i++)
                    #pragma unroll
                    for (int j = 0; j < 6; j++)
                        mma_f16(acc[i][j], af[i], &bfr[j * 2]);
            }
        }

        // flush: plain store when this CTA computed the entire job
        float* Gp = g_G[g] + (size_t)(mt * BM) * PN;
        const bool whole = (kt0 == 0) && (nseg == NTJ);
        #pragma unroll
        for (int i = 0; i < 4; i++) {
            const int r0 = wm + i * 16 + lg;
            #pragma unroll
            for (int j = 0; j < 6; j++) {
                const int c0 = wn + j * 8 + 2 * tq;
                float* p0 = &Gp[(size_t)r0 * PN + c0];
                float* p1 = &Gp[(size_t)(r0 + 8) * PN + c0];
                if (whole) {
                    *(float2*)p0 = make_float2(acc[i][j][0], acc[i][j][1]);
                    *(float2*)p1 = make_float2(acc[i][j][2], acc[i][j][3]);
                } else {
                    atomicAdd(p0,     acc[i][j][0]);
                    atomicAdd(p0 + 1, acc[i][j][1]);
                    atomicAdd(p1,     acc[i][j][2]);
                    atomicAdd(p1 + 1, acc[i][j][3]);
                }
                acc[i][j][0] = acc[i][j][1] = acc[i][j][2] = acc[i][j][3] = 0.0f;
            }
        }
        u += nseg;
    }
}

// ---------------------------------------------------------------------------
// 6) combine (float2-vectorized): Hamilton outputs + mixprop.
//    zero_g != 0 -> re-zero G panels in place for the next qgemm.
// ---------------------------------------------------------------------------
__global__ void combine_kernel(int s, int zero_g) {
    const int idx2 = blockIdx.x * blockDim.x + threadIdx.x;  // float2 index
    if (idx2 >= NN * PN / 2) return;
    const int v = idx2 / (PN / 2);
    const int c = (idx2 - v * (PN / 2)) * 2;
    const size_t o = (size_t)v * PN + c;

    float2 G[12];
    #pragma unroll
    for (int g = 0; g < 12; g++) {
        G[g] = *(const float2*)&g_G[g][o];
        if (zero_g) *(float2*)&g_G[g][o] = make_float2(0.f, 0.f);
    }

    float2 out_r, out_i, out_j, out_k;
    out_r.x = G[0].x - G[2].x - G[3].x + G[5].x;
    out_r.y = G[0].y - G[2].y - G[3].y + G[5].y;
    out_i.x = G[0].x + G[1].x - G[3].x + G[4].x;
    out_i.y = G[0].y + G[1].y - G[3].y + G[4].y;
    out_j.x = G[6].x - G[8].x + G[9].x + G[11].x;
    out_j.y = G[6].y - G[8].y + G[9].y + G[11].y;
    out_k.x = G[6].x - G[7].x + G[9].x + -G[10].x;
    out_k.y = G[6].y - G[7].y + G[9].y + -G[10].y;

    const size_t base = (size_t)v * COLS + c;
    const float* __restrict__ H0 = g_Hs[0];
    float* __restrict__ Hn = g_Hs[s + 1];
    const float2 h0r = *(const float2*)&H0[base + 0 * 96];
    const float2 h0i = *(const float2*)&H0[base + 1 * 96];
    const float2 h0j = *(const float2*)&H0[base + 2 * 96];
    const float2 h0k = *(const float2*)&H0[base + 3 * 96];
    const float B = 1.0f - ALPHA;
    *(float2*)&Hn[base + 0 * 96] =
        make_float2(ALPHA * h0r.x + B * out_r.x, ALPHA * h0r.y + B * out_r.y);
    *(float2*)&Hn[base + 1 * 96] =
        make_float2(ALPHA * h0i.x + B * out_i.x, ALPHA * h0i.y + B * out_i.y);
    *(float2*)&Hn[base + 2 * 96] =
        make_float2(ALPHA * h0j.x + B * out_j.x, ALPHA * h0j.y + B * out_j.y);
    *(float2*)&Hn[base + 3 * 96] =
        make_float2(ALPHA * h0k.x + B * out_k.x, ALPHA * h0k.y + B * out_k.y);
}

// ---------------------------------------------------------------------------
// 7) final quaternion-weight projection
// ---------------------------------------------------------------------------
__global__ void project_kernel(const float* __restrict__ weight,
                               float* __restrict__ out) {
    __shared__ float ham[GDEP + 1][16][16];
    const int   widx[4][4] = {{0,1,2,3},{1,0,3,2},{2,3,0,1},{3,2,1,0}};
    const float sgn[4][4]  = {{ 1.f,-1.f,-1.f,-1.f},
                              { 1.f, 1.f,-1.f, 1.f},
                              { 1.f, 1.f, 1.f,-1.f},
                              { 1.f,-1.f, 1.f, 1.f}};
    for (int idx = threadIdx.x; idx < (GDEP + 1) * 256; idx += blockDim.x) {
        const int k  = idx >> 8;
        const int i  = (idx >> 4) & 15;
        const int j  = idx & 15;
        const int qi = i >> 2, a = i & 3;
        const int qj = j >> 2, bb = j & 3;
        ham[k][i][j] = sgn[qj][qi] * weight[(k * 4 + a) * 16 + widx[qj][qi] * 4 + bb];
    }
    __syncthreads();

    const int gidx = blockIdx.x * blockDim.x + threadIdx.x;
    if (gidx >= NB * NN * TT) return;
    const int t = gidx % TT;
    const int n = (gidx / TT) % NN;
    const int b = gidx / (TT * NN);

    float hv[(GDEP + 1) * 16];
    #pragma unroll
    for (int k = 0; k <= GDEP; k++)
        #pragma unroll
        for (int i = 0; i < 16; i++)
            hv[k * 16 + i] =
                g_Hs[k][(size_t)n * COLS + (i >> 2) * 96 + (b * 4 + (i & 3)) * 12 + t];

    #pragma unroll
    for (int j = 0; j < 16; j++) {
        float acc = 0.0f;
        #pragma unroll
        for (int k = 0; k <= GDEP; k++)
            #pragma unroll
            for (int i = 0; i < 16; i++)
                acc += hv[k * 16 + i] * ham[k][i][j];
        out[(((size_t)b * C_OUT + j) * NN + n) * TT + t] = acc;
    }
}

// ---------------------------------------------------------------------------
extern "C" void kernel_launch(void* const* d_in, const int* in_sizes, int n_in,
                              void* d_out, int out_size) {
    const float* x  = (const float*)d_in[0];
    const float* Ar = (const float*)d_in[1];
    const float* Ai = (const float*)d_in[2];
    const float* Aj = (const float*)d_in[3];
    const float* Ak = (const float*)d_in[4];
    const float* w  = (const float*)d_in[5];
    float* out = (float*)d_out;

    cudaFuncSetAttribute(qgemm_kernel,
                         cudaFuncAttributeMaxDynamicSharedMemorySize, SM_BYTES);

    yzero_kernel<<<(12 * (int)PSZ / 4 + 255) / 256, 256>>>();
    prep_kernel<<<dim3(NN, 2), 256>>>(Ar, Ai, Aj, Ak);
    pack_kernel<<<(HSZ + 255) / 256, 256>>>(x);
    xpose_kernel<<<dim3(NN / 32, 3), dim3(32, 8)>>>(0);

    qgemm_kernel<<<NCTA, 128, SM_BYTES>>>();
    combine_kernel<<<(NN * PN / 2 + 255) / 256, 256>>>(0, 1);
    xpose_kernel<<<dim3(NN / 32, 3), dim3(32, 8)>>>(1);

    qgemm_kernel<<<NCTA, 128, SM_BYTES>>>();
    combine_kernel<<<(NN * PN / 2 + 255) / 256, 256>>>(1, 0);

    project_kernel<<<(NB * NN * TT + 255) / 256, 256>>>(w, out);
}